// round 2
// baseline (speedup 1.0000x reference)
#include <cuda_runtime.h>
#include <math.h>

// DUQ head: out[b,c,h,w] = exp( gamma/16 * sum_e ( (W[e,c,:] . feat[b,:,h,w]) - m[e,c]/N[c] )^2 )
// gamma = -1/(2*0.1^2) = -50  ->  scale = -50/16 = -3.125
//
// GEMM view: A = features[b] as [K=512, M=16384] (pixel-contiguous),
//            B = weights as [N=1024 (e,c), K=512] (K-contiguous).
// Block tile: 128 pixels x (8 channels x 16 e). 256 threads (8 warps).
// warp w -> channel c = blockIdx.x*8 + w; lane -> 4 contiguous pixels.
// Each thread accumulates acc[4 px][16 e] and does the full e-reduction +
// centroid subtraction + expf in registers. No cross-thread epilogue.

#define BK 16
#define BM 128
#define NC 8
#define NE 16

__global__ __launch_bounds__(256, 2)
void duq_kernel(const float* __restrict__ feat,
                const float* __restrict__ wgt,
                const float* __restrict__ mbuf,
                const float* __restrict__ Nbuf,
                float* __restrict__ out)
{
    __shared__ __align__(16) float As[BK][BM];          // 8 KB
    __shared__ __align__(16) float Bs[BK][NC][NE];      // 8 KB

    const int t    = threadIdx.x;
    const int lane = t & 31;
    const int w    = t >> 5;

    const int nb = blockIdx.x;                 // 0..7 channel group
    const int mb = blockIdx.y;                 // 0..1023 pixel tile
    const int tiles_per_batch = 16384 / BM;    // 128
    const int b  = mb / tiles_per_batch;
    const int p0 = (mb % tiles_per_batch) * BM;

    const float* A = feat + (size_t)b * 512 * 16384 + p0;   // A[f*16384 + p]
    const int c = nb * NC + w;

    float acc[4][16];
#pragma unroll
    for (int i = 0; i < 4; i++)
#pragma unroll
        for (int e = 0; e < 16; e++) acc[i][e] = 0.0f;

    for (int k0 = 0; k0 < 512; k0 += BK) {
        // ---- load A tile: BK x BM = 512 float4, 2 per thread, fully coalesced ----
#pragma unroll
        for (int i = 0; i < 2; i++) {
            int idx = t + i * 256;       // float4 index within tile
            int kk  = idx >> 5;          // 32 float4 per k-row
            int p4  = idx & 31;
            float4 v = *(const float4*)(A + (size_t)(k0 + kk) * 16384 + p4 * 4);
            *(float4*)(&As[kk][p4 * 4]) = v;
        }
        // ---- load B tile: 128 (e,c) rows x BK floats; thread -> half row ----
        {
            int r    = t >> 1;
            int half = (t & 1) * 8;
            int e    = r & 15;
            int cl   = r >> 4;
            const float* src = wgt + ((size_t)(e * 64 + nb * NC + cl)) * 512 + k0 + half;
            float4 v0 = *(const float4*)(src);
            float4 v1 = *(const float4*)(src + 4);
            Bs[half + 0][cl][e] = v0.x;
            Bs[half + 1][cl][e] = v0.y;
            Bs[half + 2][cl][e] = v0.z;
            Bs[half + 3][cl][e] = v0.w;
            Bs[half + 4][cl][e] = v1.x;
            Bs[half + 5][cl][e] = v1.y;
            Bs[half + 6][cl][e] = v1.z;
            Bs[half + 7][cl][e] = v1.w;
        }
        __syncthreads();

        // ---- compute: per k-step 1 LDS.128 (A) + 4 broadcast LDS.128 (B) + 64 FFMA ----
#pragma unroll
        for (int kk = 0; kk < BK; kk++) {
            float4 a4 = *(const float4*)(&As[kk][lane << 2]);
            float av[4] = {a4.x, a4.y, a4.z, a4.w};
            float bv[16];
#pragma unroll
            for (int q = 0; q < 4; q++) {
                float4 b4 = *(const float4*)(&Bs[kk][w][q << 2]);
                bv[4 * q + 0] = b4.x; bv[4 * q + 1] = b4.y;
                bv[4 * q + 2] = b4.z; bv[4 * q + 3] = b4.w;
            }
#pragma unroll
            for (int i = 0; i < 4; i++)
#pragma unroll
                for (int e = 0; e < 16; e++)
                    acc[i][e] = fmaf(av[i], bv[e], acc[i][e]);
        }
        __syncthreads();
    }

    // ---- epilogue: centroid subtract, e-mean of squares, RBF exp ----
    float invN = 1.0f / Nbuf[c];
    float cent[16];
#pragma unroll
    for (int e = 0; e < 16; e++) cent[e] = mbuf[e * 64 + c] * invN;

    const float scale = -3.125f;   // gamma / 16
    float res[4];
#pragma unroll
    for (int i = 0; i < 4; i++) {
        float s = 0.0f;
#pragma unroll
        for (int e = 0; e < 16; e++) {
            float d = acc[i][e] - cent[e];
            s = fmaf(d, d, s);
        }
        res[i] = expf(s * scale);
    }

    float* o = out + ((size_t)b * 64 + c) * 16384 + p0 + (lane << 2);
    *(float4*)o = make_float4(res[0], res[1], res[2], res[3]);
}

extern "C" void kernel_launch(void* const* d_in, const int* in_sizes, int n_in,
                              void* d_out, int out_size)
{
    const float* feat = (const float*)d_in[0];   // [8, 512, 128, 128]
    const float* wgt  = (const float*)d_in[1];   // [16, 64, 512]
    const float* m    = (const float*)d_in[2];   // [16, 64]
    const float* N    = (const float*)d_in[3];   // [64]
    float* out        = (float*)d_out;           // [8, 64, 128, 128]

    dim3 grid(8, 1024);   // x = channel groups (shares A tile across x -> L2 reuse)
    dim3 block(256);
    duq_kernel<<<grid, block>>>(feat, wgt, m, N, out);
}

// round 4
// speedup vs baseline: 2.3382x; 2.3382x over previous
#include <cuda_runtime.h>
#include <cuda_fp16.h>
#include <cstdint>
#include <math.h>

// ============================================================================
// DUQ head via legacy mma.sync (HMMA) 3xFP16-split GEMM + fused RBF epilogue.
// out[b,c,p] = exp(-3.125 * sum_e (emb[p, c*16+e] - cent[c*16+e])^2)
// emb = feat[b,:,p] . w[(c,e),:], K=512.
// a = ah+al, b = bh+bl (exact fp16 splits); acc = ah*bh + ah*bl + al*bh (fp32).
// GEMM M=131072 (pixels), N=1024 (n=c*16+e), effective K = 3*512.
// CTA tile 256x128, K-tile 64, 512 threads, 3-stage cp.async pipeline.
// ============================================================================

#define BM 256
#define BN 128
#define BK 64
#define KTILES 24            // 3 pieces * 512/64
#define STAGE_BYTES 49152    // A 32KB + B 16KB
#define OFF_B 32768
#define CENT_OFF 147456
#define SMEM_TOTAL (147456 + 512)

// -------- device-global scratch (no cudaMalloc allowed) ----------------------
__device__ __half g_ah[67108864];   // [131072 px][512 k]
__device__ __half g_al[67108864];
__device__ __half g_bh[524288];     // [1024 n][512 k], n = c*16+e
__device__ __half g_bl[524288];
__device__ float  g_cent[1024];

// -------- helpers -------------------------------------------------------------
__device__ __forceinline__ uint32_t smem_u32(const void* p) {
    uint32_t a;
    asm("{ .reg .u64 t; cvta.to.shared.u64 t, %1; cvt.u32.u64 %0, t; }" : "=r"(a) : "l"(p));
    return a;
}
__device__ __forceinline__ void cp16(uint32_t dst, const __half* src) {
    asm volatile("cp.async.cg.shared.global [%0], [%1], 16;"
                 :: "r"(dst), "l"(__cvta_generic_to_global(src)));
}
__device__ __forceinline__ void ldsm4(uint32_t* r, uint32_t addr) {
    asm volatile("ldmatrix.sync.aligned.m8n8.x4.shared.b16 {%0,%1,%2,%3}, [%4];"
                 : "=r"(r[0]), "=r"(r[1]), "=r"(r[2]), "=r"(r[3]) : "r"(addr));
}
__device__ __forceinline__ void ldsm2(uint32_t* r, uint32_t addr) {
    asm volatile("ldmatrix.sync.aligned.m8n8.x2.shared.b16 {%0,%1}, [%2];"
                 : "=r"(r[0]), "=r"(r[1]) : "r"(addr));
}
__device__ __forceinline__ void mma16816(float* c, const uint32_t* a, const uint32_t* b) {
    asm volatile("mma.sync.aligned.m16n8k16.row.col.f32.f16.f16.f32 "
                 "{%0,%1,%2,%3}, {%4,%5,%6,%7}, {%8,%9}, {%0,%1,%2,%3};"
                 : "+f"(c[0]), "+f"(c[1]), "+f"(c[2]), "+f"(c[3])
                 : "r"(a[0]), "r"(a[1]), "r"(a[2]), "r"(a[3]), "r"(b[0]), "r"(b[1]));
}

// -------- prep 1: transpose + fp16-split features ----------------------------
__global__ void prep_feat(const float* __restrict__ feat) {
    __shared__ float tile[32][33];
    int b = blockIdx.z;
    int p0 = blockIdx.x * 32, k0 = blockIdx.y * 32;
    int tx = threadIdx.x, ty = threadIdx.y;                // (32, 8)
    const float* src = feat + ((size_t)b * 512 + k0) * 16384 + p0;
#pragma unroll
    for (int i = 0; i < 4; i++)
        tile[ty + 8 * i][tx] = src[(size_t)(ty + 8 * i) * 16384 + tx];
    __syncthreads();
    size_t dbase = ((size_t)b * 16384 + p0) * 512 + k0;
#pragma unroll
    for (int i = 0; i < 4; i++) {
        int pr = ty + 8 * i;
        float v = tile[tx][pr];
        __half hi = __float2half_rn(v);
        __half lo = __float2half_rn(v - __half2float(hi));
        g_ah[dbase + (size_t)pr * 512 + tx] = hi;
        g_al[dbase + (size_t)pr * 512 + tx] = lo;
    }
}

// -------- prep 2: weights reorder + split, centroids --------------------------
__global__ void prep_w(const float* __restrict__ wgt, const float* __restrict__ m,
                       const float* __restrict__ Nb) {
    int n = blockIdx.x;                 // n = c*16 + e
    int c = n >> 4, e = n & 15;
    const float* src = wgt + ((size_t)e * 64 + c) * 512;
    for (int k = threadIdx.x; k < 512; k += 128) {
        float v = src[k];
        __half hi = __float2half_rn(v);
        g_bh[(size_t)n * 512 + k] = hi;
        g_bl[(size_t)n * 512 + k] = __float2half_rn(v - __half2float(hi));
    }
    if (threadIdx.x == 0) g_cent[n] = m[e * 64 + c] / Nb[c];
}

// -------- stage fill: 6 x 16B cp.async per thread ------------------------------
__device__ __forceinline__ void fill_stage(uint32_t sb, int s, int kt, long P0, int n0, int t) {
    int piece = kt >> 3;                          // 0: ah*bh  1: ah*bl  2: al*bh
    const __half* Asrc = (piece == 2) ? g_al : g_ah;
    const __half* Bsrc = (piece == 1) ? g_bl : g_bh;
    int kb = (kt & 7) * BK;
    uint32_t st = sb + s * STAGE_BYTES;
#pragma unroll
    for (int i = 0; i < 6; i++) {
        int g = t + i * 512;
        if (g < 2048) {                           // A: 256 rows x 8 chunks
            int r = g >> 3, c = g & 7;
            uint32_t d = st + r * 128 + ((c ^ (r & 7)) << 4);
            cp16(d, Asrc + (size_t)(P0 + r) * 512 + kb + c * 8);
        } else {                                  // B: 128 rows x 8 chunks
            int gb = g - 2048;
            int r = gb >> 3, c = gb & 7;
            uint32_t d = st + OFF_B + r * 128 + ((c ^ (r & 7)) << 4);
            cp16(d, Bsrc + (size_t)(n0 + r) * 512 + kb + c * 8);
        }
    }
}

// -------- main GEMM + fused RBF epilogue ---------------------------------------
__global__ __launch_bounds__(512, 1) void duq_mma(float* __restrict__ out) {
    extern __shared__ char smem[];
    uint32_t sb = smem_u32(smem);
    int t = threadIdx.x, l = t & 31, w = t >> 5;
    int nb = blockIdx.x, mb = blockIdx.y;
    long P0 = (long)mb * BM;           // 256 | 16384 -> never crosses a batch
    int n0 = nb * BN;

    if (t < 128) ((float*)(smem + CENT_OFF))[t] = g_cent[n0 + t];

    int wm = (w >> 2) * 64;            // warp M offset (4 groups)
    int wn = (w & 3) * 32;             // warp N offset (4 groups)

    // lane-invariant ldmatrix address parts
    int arow = (l & 7) + ((l >> 3) & 1) * 8;   // row within 16-row A frag
    int ahi  = (l >> 4) & 1;                   // k-chunk hi bit for A
    int brow = l & 7;
    int bhi  = (l >> 3) & 1;

    float acc[4][4][4];
#pragma unroll
    for (int i = 0; i < 4; i++)
#pragma unroll
        for (int j = 0; j < 4; j++)
#pragma unroll
            for (int q = 0; q < 4; q++) acc[i][j][q] = 0.0f;

    fill_stage(sb, 0, 0, P0, n0, t);
    asm volatile("cp.async.commit_group;" ::: "memory");
    fill_stage(sb, 1, 1, P0, n0, t);
    asm volatile("cp.async.commit_group;" ::: "memory");

    for (int kt = 0; kt < KTILES; kt++) {
        asm volatile("cp.async.wait_group 1;" ::: "memory");
        __syncthreads();

        if (kt + 2 < KTILES) fill_stage(sb, (kt + 2) % 3, kt + 2, P0, n0, t);
        asm volatile("cp.async.commit_group;" ::: "memory");

        uint32_t As = sb + (kt % 3) * STAGE_BYTES;
        uint32_t Bs = As + OFF_B;
#pragma unroll
        for (int k16 = 0; k16 < 4; k16++) {
            uint32_t a[4][4], b[4][2];
#pragma unroll
            for (int mf = 0; mf < 4; mf++) {
                int ra = wm + mf * 16 + arow;
                uint32_t ad = As + ra * 128 + (((2 * k16 + ahi) ^ (l & 7)) << 4);
                ldsm4(a[mf], ad);
            }
#pragma unroll
            for (int nf = 0; nf < 4; nf++) {
                int rb = wn + nf * 8 + brow;
                uint32_t bd = Bs + rb * 128 + (((2 * k16 + bhi) ^ brow) << 4);
                ldsm2(b[nf], bd);
            }
#pragma unroll
            for (int mf = 0; mf < 4; mf++)
#pragma unroll
                for (int nf = 0; nf < 4; nf++)
                    mma16816(acc[mf][nf], a[mf], b[nf]);
        }
    }

    // ---- epilogue: diff^2, 16-e reduction (2 quad shuffles), expf, store ----
    const float* centS = (const float*)(smem + CENT_OFF);
    int q2 = l & 3;
    int cbase = (n0 + wn) >> 4;        // first of the 2 channels this warp owns

#pragma unroll
    for (int mf = 0; mf < 4; mf++) {
        float s[2][2] = {{0.0f, 0.0f}, {0.0f, 0.0f}};   // [channel-half][row-half]
#pragma unroll
        for (int nf = 0; nf < 4; nf++) {
            int q = nf >> 1;
#pragma unroll
            for (int j = 0; j < 2; j++) {
                float ce = centS[wn + nf * 8 + 2 * q2 + j];
                float d0 = acc[mf][nf][j]     - ce;
                float d1 = acc[mf][nf][2 + j] - ce;
                s[q][0] = fmaf(d0, d0, s[q][0]);
                s[q][1] = fmaf(d1, d1, s[q][1]);
            }
        }
#pragma unroll
        for (int q = 0; q < 2; q++)
#pragma unroll
            for (int r = 0; r < 2; r++) {
                s[q][r] += __shfl_xor_sync(0xFFFFFFFFu, s[q][r], 1);
                s[q][r] += __shfl_xor_sync(0xFFFFFFFFu, s[q][r], 2);
            }
        float va = (l & 1) ? s[1][0] : s[0][0];
        float vb = (l & 1) ? s[1][1] : s[0][1];
        float v  = (l & 2) ? vb : va;
        float o  = expf(-3.125f * v);

        long gp = P0 + wm + mf * 16 + ((l >> 2) & 7) + ((l & 2) << 2);
        int b   = (int)(gp >> 14);
        int pin = (int)(gp & 16383);
        int ch  = cbase + (l & 1);
        out[((size_t)b * 64 + ch) * 16384 + pin] = o;
    }
}

// -------- launch ----------------------------------------------------------------
extern "C" void kernel_launch(void* const* d_in, const int* in_sizes, int n_in,
                              void* d_out, int out_size)
{
    const float* feat = (const float*)d_in[0];   // [8, 512, 128, 128]
    const float* wgt  = (const float*)d_in[1];   // [16, 64, 512]
    const float* m    = (const float*)d_in[2];   // [16, 64]
    const float* N    = (const float*)d_in[3];   // [64]
    float* out        = (float*)d_out;           // [8, 64, 128, 128]

    cudaFuncSetAttribute(duq_mma, cudaFuncAttributeMaxDynamicSharedMemorySize, SMEM_TOTAL);

    prep_feat<<<dim3(512, 16, 8), dim3(32, 8)>>>(feat);
    prep_w<<<1024, 128>>>(wgt, m, N);
    duq_mma<<<dim3(8, 512), 512, SMEM_TOTAL>>>(out);
}

// round 5
// speedup vs baseline: 2.3806x; 1.0181x over previous
#include <cuda_runtime.h>
#include <cuda_fp16.h>
#include <cstdint>
#include <math.h>

// ============================================================================
// DUQ head via mma.sync (HMMA) 3xFP16-split GEMM + fused RBF epilogue.
// out[b,c,p] = exp(-3.125 * sum_e (emb[p, c*16+e] - cent[c*16+e])^2)
// emb = feat[b,:,p] . w[(c,e),:], K=512.
// a = ah+al, b = bh+bl (exact fp16 splits); acc = ah*bh + ah*bl + al*bh (fp32).
// GEMM M=131072, N=1024 (n=c*16+e), effective K = 3*512.
// CTA tile 256x128, warp tile 64x64 (8 warps / 256 thr), K-tile 64,
// 3-stage cp.async pipeline. Warp tile doubled vs R4 to halve smem reads/MAC.
// ============================================================================

#define BM 256
#define BN 128
#define BK 64
#define KTILES 24            // 3 pieces * 512/64
#define STAGE_BYTES 49152    // A 32KB + B 16KB
#define OFF_B 32768
#define CENT_OFF 147456
#define SMEM_TOTAL (147456 + 512)

// -------- device-global scratch (no cudaMalloc allowed) ----------------------
__device__ __half g_ah[67108864];   // [131072 px][512 k]
__device__ __half g_al[67108864];
__device__ __half g_bh[524288];     // [1024 n][512 k], n = c*16+e
__device__ __half g_bl[524288];
__device__ float  g_cent[1024];

// -------- helpers -------------------------------------------------------------
__device__ __forceinline__ uint32_t smem_u32(const void* p) {
    uint32_t a;
    asm("{ .reg .u64 t; cvta.to.shared.u64 t, %1; cvt.u32.u64 %0, t; }" : "=r"(a) : "l"(p));
    return a;
}
__device__ __forceinline__ void cp16(uint32_t dst, const __half* src) {
    asm volatile("cp.async.cg.shared.global [%0], [%1], 16;"
                 :: "r"(dst), "l"(__cvta_generic_to_global(src)));
}
__device__ __forceinline__ void ldsm4(uint32_t* r, uint32_t addr) {
    asm volatile("ldmatrix.sync.aligned.m8n8.x4.shared.b16 {%0,%1,%2,%3}, [%4];"
                 : "=r"(r[0]), "=r"(r[1]), "=r"(r[2]), "=r"(r[3]) : "r"(addr));
}
__device__ __forceinline__ void mma16816(float* c, const uint32_t* a, const uint32_t* b) {
    asm volatile("mma.sync.aligned.m16n8k16.row.col.f32.f16.f16.f32 "
                 "{%0,%1,%2,%3}, {%4,%5,%6,%7}, {%8,%9}, {%0,%1,%2,%3};"
                 : "+f"(c[0]), "+f"(c[1]), "+f"(c[2]), "+f"(c[3])
                 : "r"(a[0]), "r"(a[1]), "r"(a[2]), "r"(a[3]), "r"(b[0]), "r"(b[1]));
}

// -------- prep 1: transpose + fp16-split features ----------------------------
__global__ void prep_feat(const float* __restrict__ feat) {
    __shared__ float tile[32][33];
    int b = blockIdx.z;
    int p0 = blockIdx.x * 32, k0 = blockIdx.y * 32;
    int tx = threadIdx.x, ty = threadIdx.y;                // (32, 8)
    const float* src = feat + ((size_t)b * 512 + k0) * 16384 + p0;
#pragma unroll
    for (int i = 0; i < 4; i++)
        tile[ty + 8 * i][tx] = src[(size_t)(ty + 8 * i) * 16384 + tx];
    __syncthreads();
    size_t dbase = ((size_t)b * 16384 + p0) * 512 + k0;
#pragma unroll
    for (int i = 0; i < 4; i++) {
        int pr = ty + 8 * i;
        float v = tile[tx][pr];
        __half hi = __float2half_rn(v);
        __half lo = __float2half_rn(v - __half2float(hi));
        g_ah[dbase + (size_t)pr * 512 + tx] = hi;
        g_al[dbase + (size_t)pr * 512 + tx] = lo;
    }
}

// -------- prep 2: weights reorder + split, centroids --------------------------
__global__ void prep_w(const float* __restrict__ wgt, const float* __restrict__ m,
                       const float* __restrict__ Nb) {
    int n = blockIdx.x;                 // n = c*16 + e
    int c = n >> 4, e = n & 15;
    const float* src = wgt + ((size_t)e * 64 + c) * 512;
    for (int k = threadIdx.x; k < 512; k += 128) {
        float v = src[k];
        __half hi = __float2half_rn(v);
        g_bh[(size_t)n * 512 + k] = hi;
        g_bl[(size_t)n * 512 + k] = __float2half_rn(v - __half2float(hi));
    }
    if (threadIdx.x == 0) g_cent[n] = m[e * 64 + c] / Nb[c];
}

// -------- stage fill (256 threads): 12 x 16B cp.async per thread ---------------
__device__ __forceinline__ void fill_stage(uint32_t sb, int s, int kt, long P0, int n0, int t) {
    int piece = kt >> 3;                          // 0: ah*bh  1: ah*bl  2: al*bh
    const __half* Asrc = (piece == 2) ? g_al : g_ah;
    const __half* Bsrc = (piece == 1) ? g_bl : g_bh;
    int kb = (kt & 7) * BK;
    uint32_t st = sb + s * STAGE_BYTES;
#pragma unroll
    for (int i = 0; i < 8; i++) {                 // A: 256 rows x 8 chunks
        int g = t + i * 256;
        int r = g >> 3, c = g & 7;
        uint32_t d = st + r * 128 + ((c ^ (r & 7)) << 4);
        cp16(d, Asrc + (size_t)(P0 + r) * 512 + kb + c * 8);
    }
#pragma unroll
    for (int i = 0; i < 4; i++) {                 // B: 128 rows x 8 chunks
        int g = t + i * 256;
        int r = g >> 3, c = g & 7;
        uint32_t d = st + OFF_B + r * 128 + ((c ^ (r & 7)) << 4);
        cp16(d, Bsrc + (size_t)(n0 + r) * 512 + kb + c * 8);
    }
}

// -------- main GEMM + fused RBF epilogue ---------------------------------------
__global__ __launch_bounds__(256, 1) void duq_mma(float* __restrict__ out) {
    extern __shared__ char smem[];
    uint32_t sb = smem_u32(smem);
    int t = threadIdx.x, l = t & 31, w = t >> 5;
    int nb = blockIdx.x, mb = blockIdx.y;
    long P0 = (long)mb * BM;           // 256 | 16384 -> never crosses a batch
    int n0 = nb * BN;

    if (t < 128) ((float*)(smem + CENT_OFF))[t] = g_cent[n0 + t];

    int wm = (w >> 1) * 64;            // 4 M-groups of 64
    int wn = (w & 1) * 64;             // 2 N-groups of 64

    // ldmatrix lane-address components (identical mapping to R4, proven)
    int rl  = l & 7;                   // row within 8-row matrix
    int mh  = (l >> 3) & 1;            // matrix half bit
    int hi  = (l >> 4) & 1;            // upper pair bit

    float acc[4][8][4];
#pragma unroll
    for (int i = 0; i < 4; i++)
#pragma unroll
        for (int j = 0; j < 8; j++)
#pragma unroll
            for (int q = 0; q < 4; q++) acc[i][j][q] = 0.0f;

    fill_stage(sb, 0, 0, P0, n0, t);
    asm volatile("cp.async.commit_group;" ::: "memory");
    fill_stage(sb, 1, 1, P0, n0, t);
    asm volatile("cp.async.commit_group;" ::: "memory");

    for (int kt = 0; kt < KTILES; kt++) {
        asm volatile("cp.async.wait_group 1;" ::: "memory");
        __syncthreads();

        if (kt + 2 < KTILES) fill_stage(sb, (kt + 2) % 3, kt + 2, P0, n0, t);
        asm volatile("cp.async.commit_group;" ::: "memory");

        uint32_t As = sb + (kt % 3) * STAGE_BYTES;
        uint32_t Bs = As + OFF_B;
#pragma unroll
        for (int k16 = 0; k16 < 4; k16++) {
            uint32_t a[4][4], b[4][4];
            // A frags: rows 0-7 klo | rows 8-15 klo | rows 0-7 khi | rows 8-15 khi
#pragma unroll
            for (int mf = 0; mf < 4; mf++) {
                int ra = wm + mf * 16 + rl + mh * 8;
                uint32_t ad = As + ra * 128 + (((2 * k16 + hi) ^ (ra & 7)) << 4);
                ldsm4(a[mf], ad);
            }
            // B frags via x4: lanes 0-15 -> n rows 0-7 (klo,khi) = nf even,
            //                 lanes 16-31 -> n rows 8-15            = nf odd
#pragma unroll
            for (int np = 0; np < 4; np++) {
                int rb = wn + np * 16 + rl + hi * 8;
                uint32_t bd = Bs + rb * 128 + (((2 * k16 + mh) ^ (rb & 7)) << 4);
                ldsm4(b[np], bd);
            }
#pragma unroll
            for (int mf = 0; mf < 4; mf++)
#pragma unroll
                for (int np = 0; np < 4; np++) {
                    mma16816(acc[mf][2 * np],     a[mf], &b[np][0]);
                    mma16816(acc[mf][2 * np + 1], a[mf], &b[np][2]);
                }
        }
    }

    // ---- epilogue: diff^2, e-reduction (quad shuffles), expf, store ----
    const float* centS = (const float*)(smem + CENT_OFF);
    int q2 = l & 3;
    int cb = ((n0 + wn) >> 4);         // first of this warp's 4 channels

#pragma unroll
    for (int mf = 0; mf < 4; mf++) {
        float s[4][2];
#pragma unroll
        for (int ch = 0; ch < 4; ch++) { s[ch][0] = 0.0f; s[ch][1] = 0.0f; }
#pragma unroll
        for (int nf = 0; nf < 8; nf++) {
            int ch = nf >> 1;
#pragma unroll
            for (int j = 0; j < 2; j++) {
                float ce = centS[wn + nf * 8 + 2 * q2 + j];
                float d0 = acc[mf][nf][j]     - ce;
                float d1 = acc[mf][nf][2 + j] - ce;
                s[ch][0] = fmaf(d0, d0, s[ch][0]);
                s[ch][1] = fmaf(d1, d1, s[ch][1]);
            }
        }
#pragma unroll
        for (int ch = 0; ch < 4; ch++)
#pragma unroll
            for (int r = 0; r < 2; r++) {
                s[ch][r] += __shfl_xor_sync(0xFFFFFFFFu, s[ch][r], 1);
                s[ch][r] += __shfl_xor_sync(0xFFFFFFFFu, s[ch][r], 2);
            }
        // lane's quad-index selects its channel
        float v0 = (q2 == 0) ? s[0][0] : (q2 == 1) ? s[1][0] : (q2 == 2) ? s[2][0] : s[3][0];
        float v1 = (q2 == 0) ? s[0][1] : (q2 == 1) ? s[1][1] : (q2 == 2) ? s[2][1] : s[3][1];

        long gp = P0 + wm + mf * 16 + (l >> 2);
        int b   = (int)(gp >> 14);
        int pin = (int)(gp & 16383);
        int ch  = cb + q2;
        float* o = out + ((size_t)b * 64 + ch) * 16384 + pin;
        o[0] = expf(-3.125f * v0);
        o[8] = expf(-3.125f * v1);
    }
}

// -------- launch ----------------------------------------------------------------
extern "C" void kernel_launch(void* const* d_in, const int* in_sizes, int n_in,
                              void* d_out, int out_size)
{
    const float* feat = (const float*)d_in[0];   // [8, 512, 128, 128]
    const float* wgt  = (const float*)d_in[1];   // [16, 64, 512]
    const float* m    = (const float*)d_in[2];   // [16, 64]
    const float* N    = (const float*)d_in[3];   // [64]
    float* out        = (float*)d_out;           // [8, 64, 128, 128]

    cudaFuncSetAttribute(duq_mma, cudaFuncAttributeMaxDynamicSharedMemorySize, SMEM_TOTAL);

    prep_feat<<<dim3(512, 16, 8), dim3(32, 8)>>>(feat);
    prep_w<<<1024, 128>>>(wgt, m, N);
    duq_mma<<<dim3(8, 512), 256, SMEM_TOTAL>>>(out);
}